// round 16
// baseline (speedup 1.0000x reference)
#include <cuda_runtime.h>
#include <cuda_fp16.h>
#include <cstdint>

#define N_NODES   100000
#define N_EDGES   1600000
#define N_FEAT    128
#define N_WORKERS 4
#define N_ROWS    (N_WORKERS * N_NODES)               // 400000 flattened rows
#define SCAN_B    1024
#define N_SBLK    ((N_NODES + SCAN_B - 1) / SCAN_B)   // 98
#define APAD      136                                 // padded half-stride (conflict-free)
#define SPAD      68                                  // padded u32-stride for staging

typedef unsigned long long u64;

// Scratch (static device arrays; no allocation).
__device__ unsigned g_deg [2 * N_ROWS];               // [out | in] raw counts
__device__ float    g_dinv[2 * N_ROWS];               // [out | in] deg^-1/2 (clipped)
__device__ int      g_is64;
__device__ unsigned g_off [N_ROWS];                   // CSR row offsets (by dst)
__device__ unsigned g_cur [N_ROWS];                   // fill cursors
__device__ unsigned g_bsum[N_WORKERS * N_SBLK];       // scan block sums
__device__ int      g_csr [N_WORKERS * N_EDGES];      // src ids grouped by dst
__device__ __align__(16) __half   g_w16[N_FEAT * N_FEAT];  // W^T in fp16
__device__ __align__(16) __half2  g_x16[(long long)N_ROWS * (N_FEAT / 2)];

// ---------------------------------------------------------------------------
// int64 vs int32 index detection (indices < 100000 -> odd words zero iff i64).
// ---------------------------------------------------------------------------
__global__ void detect_idx_kernel(const unsigned int* __restrict__ p) {
    __shared__ int any;
    if (threadIdx.x == 0) any = 0;
    __syncthreads();
    if (p[2 * threadIdx.x + 1] != 0u) any = 1;
    __syncthreads();
    if (threadIdx.x == 0) g_is64 = (any == 0) ? 1 : 0;
}

__device__ __forceinline__ int load_idx(const void* p, long long i, int is64) {
    if (is64) return (int)((const long long*)p)[i];
    return ((const int*)p)[i];
}

// ---------------------------------------------------------------------------
// One-shot W^T -> fp16 (32x32 smem tile transpose, coalesced both sides).
// g_w16[n*128 + f] = fp16(W[f*128 + n])
// ---------------------------------------------------------------------------
__global__ void wt16_kernel(const float* __restrict__ weight) {
    __shared__ __half tile[32][33];
    int tx = threadIdx.x & 31, ty = threadIdx.x >> 5;   // 256 thr: ty 0..7
    int f0 = blockIdx.y * 32, n0 = blockIdx.x * 32;
#pragma unroll
    for (int r = 0; r < 4; r++) {
        int f = ty * 4 + r;
        tile[f][tx] = __float2half_rn(weight[(f0 + f) * N_FEAT + n0 + tx]);
    }
    __syncthreads();
#pragma unroll
    for (int r = 0; r < 4; r++) {
        int n = ty * 4 + r;
        g_w16[(n0 + n) * N_FEAT + f0 + tx] = tile[tx][n];
    }
}

// ---------------------------------------------------------------------------
// Degree counting (all workers, grid.y = worker).
// ---------------------------------------------------------------------------
__global__ void degree_kernel(const void* __restrict__ src, const void* __restrict__ dst) {
    int is64 = g_is64;
    int w = blockIdx.y;
    long long base = (long long)w * N_EDGES;
    for (int e = blockIdx.x * blockDim.x + threadIdx.x; e < N_EDGES;
         e += gridDim.x * blockDim.x) {
        int s = load_idx(src, base + e, is64);
        int d = load_idx(dst, base + e, is64);
        atomicAdd(&g_deg[w * N_NODES + s], 1u);
        atomicAdd(&g_deg[N_ROWS + w * N_NODES + d], 1u);
    }
}

// ---------------------------------------------------------------------------
// Exclusive scan of in-degrees -> CSR offsets.
// ---------------------------------------------------------------------------
__global__ void scan1_kernel() {
    __shared__ unsigned s[SCAN_B];
    int w = blockIdx.y;
    int i = blockIdx.x * SCAN_B + threadIdx.x;
    unsigned v = (i < N_NODES) ? g_deg[N_ROWS + w * N_NODES + i] : 0u;
    s[threadIdx.x] = v;
    __syncthreads();
    for (int d = 1; d < SCAN_B; d <<= 1) {
        unsigned t = (threadIdx.x >= d) ? s[threadIdx.x - d] : 0u;
        __syncthreads();
        s[threadIdx.x] += t;
        __syncthreads();
    }
    if (i < N_NODES) g_off[w * N_NODES + i] = s[threadIdx.x] - v;  // exclusive
    if (threadIdx.x == SCAN_B - 1) g_bsum[w * N_SBLK + blockIdx.x] = s[threadIdx.x];
}

// Warp-per-worker shuffle scan of the 98 block sums (measured ~5us).
__global__ void scan2_kernel() {
    int w = threadIdx.x >> 5;
    int lane = threadIdx.x & 31;
    unsigned carry = 0;
    for (int b0 = 0; b0 < N_SBLK; b0 += 32) {
        int b = b0 + lane;
        unsigned v = (b < N_SBLK) ? g_bsum[w * N_SBLK + b] : 0u;
        unsigned x = v;
#pragma unroll
        for (int d = 1; d < 32; d <<= 1) {
            unsigned y = __shfl_up_sync(0xFFFFFFFFu, x, d);
            if (lane >= d) x += y;
        }
        if (b < N_SBLK) g_bsum[w * N_SBLK + b] = x - v + carry;   // exclusive
        carry += __shfl_sync(0xFFFFFFFFu, x, 31);
    }
}

// scan3 + dinv fused (same node range; dinv needed only from here on).
__global__ void scan3_kernel() {
    int w = blockIdx.y;
    int i = blockIdx.x * 256 + threadIdx.x;
    if (i < N_NODES) {
        g_off[w * N_NODES + i] += g_bsum[w * N_SBLK + i / SCAN_B];
        float co = (float)g_deg[w * N_NODES + i];
        float ci = (float)g_deg[N_ROWS + w * N_NODES + i];
        g_dinv[w * N_NODES + i]          = rsqrtf(fmaxf(co, 1.0f));
        g_dinv[N_ROWS + w * N_NODES + i] = rsqrtf(fmaxf(ci, 1.0f));
    }
}

// ---------------------------------------------------------------------------
// CSR fill: bucket src ids by dst. Small 4B atomics only; zero smem.
// ---------------------------------------------------------------------------
__global__ void fill_kernel(const void* __restrict__ src, const void* __restrict__ dst) {
    int is64 = g_is64;
    int w = blockIdx.y;
    long long base = (long long)w * N_EDGES;
    for (int e = blockIdx.x * blockDim.x + threadIdx.x; e < N_EDGES;
         e += gridDim.x * blockDim.x) {
        int s = load_idx(src, base + e, is64);
        int d = load_idx(dst, base + e, is64);
        unsigned pos = g_off[w * N_NODES + d] + atomicAdd(&g_cur[w * N_NODES + d], 1u);
        g_csr[base + pos] = s;
    }
}

// ---------------------------------------------------------------------------
// HMMA GEMM: X16[r] = fp16( (feat[r]*outdeg^-1/2) @ W ), tile M=128,N=128,K=128.
// mma.sync.m16n8k16.row.col f32.f16.f16.f32. 8 warps; warp = 16-row strip.
// W^T comes pre-transposed fp16 from g_w16 (coalesced uint4 smem fill).
// Pad-136 rows: row base bank = 4*row mod 32, lanes add 0..3 -> all 32 banks.
// ---------------------------------------------------------------------------
#define SMEM_TOT (2 * 128 * APAD * 2)   // 69632 B

__global__ void __launch_bounds__(256)
gemm_mma_kernel(const float* __restrict__ feats) {
    extern __shared__ __half smh[];
    __half* As = smh;                  // 128 x APAD
    __half* Wt = smh + 128 * APAD;     // 128 x APAD;  Wt[n][k] = W[k][n]
    int t = threadIdx.x, lane = t & 31, wid = t >> 5;
    int gid = lane >> 2, tig = lane & 3;
    long long r0 = (long long)blockIdx.x * 128;

    // A tile: 128 rows x 128 f32 -> fp16 scaled by outdeg^-1/2
    {
        const float4* srcA = (const float4*)(feats + r0 * N_FEAT);
#pragma unroll 4
        for (int i = t; i < 128 * 32; i += 256) {
            int row = i >> 5, c4 = i & 31;
            float sc = g_dinv[r0 + row];
            float4 v = srcA[i];
            __half2 h0 = __floats2half2_rn(v.x * sc, v.y * sc);
            __half2 h1 = __floats2half2_rn(v.z * sc, v.w * sc);
            *(uint2*)(As + row * APAD + c4 * 4) =
                make_uint2(*(uint32_t*)&h0, *(uint32_t*)&h1);
        }
    }
    // W^T tile: coalesced uint4 from pre-transposed fp16 global
    {
        const uint4* wsrc = (const uint4*)g_w16;
#pragma unroll
        for (int i = t; i < 128 * 16; i += 256) {
            int row = i >> 4, c8 = i & 15;
            *(uint4*)(Wt + row * APAD + c8 * 8) = wsrc[i];
        }
    }
    __syncthreads();

    float c[16][4];
#pragma unroll
    for (int j = 0; j < 16; j++)
#pragma unroll
        for (int i = 0; i < 4; i++) c[j][i] = 0.0f;

    int m0 = wid * 16;
    const __half* ar0 = As + (m0 + gid) * APAD + 2 * tig;
    const __half* ar1 = ar0 + 8 * APAD;

#pragma unroll
    for (int ks = 0; ks < 8; ks++) {
        int k0 = ks * 16;
        uint32_t a0 = *(const uint32_t*)(ar0 + k0);
        uint32_t a1 = *(const uint32_t*)(ar1 + k0);
        uint32_t a2 = *(const uint32_t*)(ar0 + k0 + 8);
        uint32_t a3 = *(const uint32_t*)(ar1 + k0 + 8);
        const __half* bp = Wt + gid * APAD + k0 + 2 * tig;
#pragma unroll
        for (int j = 0; j < 16; j++) {
            uint32_t b0 = *(const uint32_t*)(bp);
            uint32_t b1 = *(const uint32_t*)(bp + 8);
            bp += 8 * APAD;
            asm volatile(
                "mma.sync.aligned.m16n8k16.row.col.f32.f16.f16.f32 "
                "{%0,%1,%2,%3}, {%4,%5,%6,%7}, {%8,%9}, {%0,%1,%2,%3};"
                : "+f"(c[j][0]), "+f"(c[j][1]), "+f"(c[j][2]), "+f"(c[j][3])
                : "r"(a0), "r"(a1), "r"(a2), "r"(a3), "r"(b0), "r"(b1));
        }
    }

    // Epilogue: frags -> padded staging (reuses A region) -> coalesced uint4 STG
    __syncthreads();
    uint32_t* stg = (uint32_t*)As;     // 128 x SPAD u32 = 34816 B (= A region)
#pragma unroll
    for (int j = 0; j < 16; j++) {
        __half2 h0 = __floats2half2_rn(c[j][0], c[j][1]);
        __half2 h1 = __floats2half2_rn(c[j][2], c[j][3]);
        stg[(m0 + gid)     * SPAD + 4 * j + tig] = *(uint32_t*)&h0;
        stg[(m0 + gid + 8) * SPAD + 4 * j + tig] = *(uint32_t*)&h1;
    }
    __syncthreads();
    uint4* outp = (uint4*)(g_x16 + r0 * (N_FEAT / 2));
#pragma unroll
    for (int i = 0; i < 8; i++) {
        int idx = t + i * 256;         // 2048 uint4 = 128 rows x 16
        int rr = idx >> 4, j4 = idx & 15;
        const uint32_t* p = stg + rr * SPAD + j4 * 4;
        outp[idx] = make_uint4(p[0], p[1], p[2], p[3]);
    }
}

// ---------------------------------------------------------------------------
// Gather: out[r] = indeg(r)^-1/2 * sum_{s in CSR[r]} X16[s] + bias.
// Warp per row, zero smem -> full occupancy; pure L2-BW bound.
// ---------------------------------------------------------------------------
__global__ void __launch_bounds__(256)
gather_kernel(const float* __restrict__ bias, float* __restrict__ out) {
    int lane = threadIdx.x & 31;
    long long r = (long long)((blockIdx.x * blockDim.x + threadIdx.x) >> 5);
    if (r >= N_ROWS) return;
    int w = (int)(r / N_NODES);

    unsigned st  = g_off[r];
    unsigned deg = g_deg[N_ROWS + r];
    const int* ep = g_csr + (long long)w * N_EDGES + st;
    const __half2* xw = g_x16 + (long long)w * N_NODES * (N_FEAT / 2);

    float4 acc = make_float4(0.f, 0.f, 0.f, 0.f);
#pragma unroll 4
    for (unsigned j = 0; j < deg; j++) {
        int s = ep[j];                                  // broadcast 4B
        uint2 u = *(const uint2*)(xw + (long long)s * (N_FEAT / 2) + lane * 2);
        float2 f01 = __half22float2(*(const __half2*)&u.x);
        float2 f23 = __half22float2(*(const __half2*)&u.y);
        acc.x += f01.x; acc.y += f01.y;
        acc.z += f23.x; acc.w += f23.y;
    }
    float si = g_dinv[N_ROWS + r];
    float4 bv = *((const float4*)bias + lane);
    float4 o;
    o.x = acc.x * si + bv.x;
    o.y = acc.y * si + bv.y;
    o.z = acc.z * si + bv.z;
    o.w = acc.w * si + bv.w;
    *((float4*)(out + r * N_FEAT) + lane) = o;
}

// ---------------------------------------------------------------------------
extern "C" void kernel_launch(void* const* d_in, const int* in_sizes, int n_in,
                              void* d_out, int out_size) {
    const float* feats  = (const float*)d_in[0];
    const float* weight = (const float*)d_in[1];
    const float* bias   = (const float*)d_in[2];
    const void*  src    = d_in[3];
    const void*  dst    = d_in[4];
    float* out = (float*)d_out;

    void* p = nullptr;
    cudaGetSymbolAddress(&p, g_deg);
    cudaMemsetAsync(p, 0, sizeof(unsigned) * 2 * N_ROWS);
    cudaGetSymbolAddress(&p, g_cur);
    cudaMemsetAsync(p, 0, sizeof(unsigned) * N_ROWS);

    detect_idx_kernel<<<1, 256>>>((const unsigned int*)src);

    dim3 wtg(4, 4);
    wt16_kernel<<<wtg, 256>>>(weight);

    dim3 dgrid(2048, N_WORKERS);
    degree_kernel<<<dgrid, 256>>>(src, dst);

    dim3 sgrid1(N_SBLK, N_WORKERS);
    scan1_kernel<<<sgrid1, SCAN_B>>>();
    scan2_kernel<<<1, 128>>>();
    dim3 sgrid3((N_NODES + 255) / 256, N_WORKERS);
    scan3_kernel<<<sgrid3, 256>>>();   // also produces dinv (out+in)

    fill_kernel<<<dgrid, 256>>>(src, dst);

    cudaFuncSetAttribute(gemm_mma_kernel, cudaFuncAttributeMaxDynamicSharedMemorySize,
                         SMEM_TOT);
    gemm_mma_kernel<<<N_ROWS / 128, 256, SMEM_TOT>>>(feats);

    gather_kernel<<<(N_ROWS * 32 + 255) / 256, 256>>>(bias, out);
}

// round 17
// speedup vs baseline: 1.2753x; 1.2753x over previous
#include <cuda_runtime.h>
#include <cuda_fp16.h>
#include <cstdint>

#define N_NODES   100000
#define N_EDGES   1600000
#define N_FEAT    128
#define N_WORKERS 4
#define N_ROWS    (N_WORKERS * N_NODES)               // 400000 flattened rows
#define SCAN_B    1024
#define N_SBLK    ((N_NODES + SCAN_B - 1) / SCAN_B)   // 98
#define APAD      136                                 // padded half-stride (conflict-free)
#define SPAD      68                                  // padded u32-stride for staging

typedef unsigned long long u64;

// Scratch (static device arrays; no allocation).
__device__ unsigned g_deg [2 * N_ROWS];               // [out | in] raw counts
__device__ float    g_dinv[2 * N_ROWS];               // [out | in] deg^-1/2 (clipped)
__device__ int      g_is64;
__device__ unsigned g_off [N_ROWS];                   // CSR row offsets (by dst)
__device__ unsigned g_cur [N_ROWS];                   // fill cursors
__device__ unsigned g_bsum[N_WORKERS * N_SBLK];       // scan block sums
__device__ int      g_csr [N_WORKERS * N_EDGES];      // src ids grouped by dst
__device__ __align__(16) __half2 g_x16[(long long)N_ROWS * (N_FEAT / 2)];

// ---------------------------------------------------------------------------
// int64 vs int32 index detection (indices < 100000 -> odd words zero iff i64).
// ---------------------------------------------------------------------------
__global__ void detect_idx_kernel(const unsigned int* __restrict__ p) {
    __shared__ int any;
    if (threadIdx.x == 0) any = 0;
    __syncthreads();
    if (p[2 * threadIdx.x + 1] != 0u) any = 1;
    __syncthreads();
    if (threadIdx.x == 0) g_is64 = (any == 0) ? 1 : 0;
}

__device__ __forceinline__ int load_idx(const void* p, long long i, int is64) {
    if (is64) return (int)((const long long*)p)[i];
    return ((const int*)p)[i];
}

// ---------------------------------------------------------------------------
// Degree counting (all workers, grid.y = worker).
// ---------------------------------------------------------------------------
__global__ void degree_kernel(const void* __restrict__ src, const void* __restrict__ dst) {
    int is64 = g_is64;
    int w = blockIdx.y;
    long long base = (long long)w * N_EDGES;
    for (int e = blockIdx.x * blockDim.x + threadIdx.x; e < N_EDGES;
         e += gridDim.x * blockDim.x) {
        int s = load_idx(src, base + e, is64);
        int d = load_idx(dst, base + e, is64);
        atomicAdd(&g_deg[w * N_NODES + s], 1u);
        atomicAdd(&g_deg[N_ROWS + w * N_NODES + d], 1u);
    }
}

// ---------------------------------------------------------------------------
// Exclusive scan of in-degrees -> CSR offsets.
// ---------------------------------------------------------------------------
__global__ void scan1_kernel() {
    __shared__ unsigned s[SCAN_B];
    int w = blockIdx.y;
    int i = blockIdx.x * SCAN_B + threadIdx.x;
    unsigned v = (i < N_NODES) ? g_deg[N_ROWS + w * N_NODES + i] : 0u;
    s[threadIdx.x] = v;
    __syncthreads();
    for (int d = 1; d < SCAN_B; d <<= 1) {
        unsigned t = (threadIdx.x >= d) ? s[threadIdx.x - d] : 0u;
        __syncthreads();
        s[threadIdx.x] += t;
        __syncthreads();
    }
    if (i < N_NODES) g_off[w * N_NODES + i] = s[threadIdx.x] - v;  // exclusive
    if (threadIdx.x == SCAN_B - 1) g_bsum[w * N_SBLK + blockIdx.x] = s[threadIdx.x];
}

// Warp-per-worker shuffle scan of the 98 block sums (measured ~5us).
__global__ void scan2_kernel() {
    int w = threadIdx.x >> 5;
    int lane = threadIdx.x & 31;
    unsigned carry = 0;
    for (int b0 = 0; b0 < N_SBLK; b0 += 32) {
        int b = b0 + lane;
        unsigned v = (b < N_SBLK) ? g_bsum[w * N_SBLK + b] : 0u;
        unsigned x = v;
#pragma unroll
        for (int d = 1; d < 32; d <<= 1) {
            unsigned y = __shfl_up_sync(0xFFFFFFFFu, x, d);
            if (lane >= d) x += y;
        }
        if (b < N_SBLK) g_bsum[w * N_SBLK + b] = x - v + carry;   // exclusive
        carry += __shfl_sync(0xFFFFFFFFu, x, 31);
    }
}

// scan3 + dinv fused (same node range; dinv needed only downstream of here).
__global__ void scan3_kernel() {
    int w = blockIdx.y;
    int i = blockIdx.x * 256 + threadIdx.x;
    if (i < N_NODES) {
        g_off[w * N_NODES + i] += g_bsum[w * N_SBLK + i / SCAN_B];
        float co = (float)g_deg[w * N_NODES + i];
        float ci = (float)g_deg[N_ROWS + w * N_NODES + i];
        g_dinv[w * N_NODES + i]          = rsqrtf(fmaxf(co, 1.0f));
        g_dinv[N_ROWS + w * N_NODES + i] = rsqrtf(fmaxf(ci, 1.0f));
    }
}

// ---------------------------------------------------------------------------
// HMMA GEMM (exact R13 version): X16[r] = fp16( (feat[r]*outdeg^-1/2) @ W ),
// tile M=128,N=128,K=128. mma.sync.m16n8k16.row.col f32.f16.f16.f32.
// 8 warps; warp = 16-row strip. Inline W^T transpose into smem (proven fast).
// Pad-136 rows: row base bank = 4*row mod 32, lanes add 0..3 -> all 32 banks.
// ---------------------------------------------------------------------------
#define SMEM_TOT (2 * 128 * APAD * 2)   // 69632 B

__global__ void __launch_bounds__(256)
gemm_mma_kernel(const float* __restrict__ feats, const float* __restrict__ weight) {
    extern __shared__ __half smh[];
    __half* As = smh;                  // 128 x APAD
    __half* Wt = smh + 128 * APAD;     // 128 x APAD;  Wt[n][k] = W[k][n]
    int t = threadIdx.x, lane = t & 31, wid = t >> 5;
    int gid = lane >> 2, tig = lane & 3;
    long long r0 = (long long)blockIdx.x * 128;

    // A tile: 128 rows x 128 f32 -> fp16 scaled by outdeg^-1/2
    {
        const float4* srcA = (const float4*)(feats + r0 * N_FEAT);
#pragma unroll 4
        for (int i = t; i < 128 * 32; i += 256) {
            int row = i >> 5, c4 = i & 31;
            float sc = g_dinv[r0 + row];
            float4 v = srcA[i];
            __half2 h0 = __floats2half2_rn(v.x * sc, v.y * sc);
            __half2 h1 = __floats2half2_rn(v.z * sc, v.w * sc);
            *(uint2*)(As + row * APAD + c4 * 4) =
                make_uint2(*(uint32_t*)&h0, *(uint32_t*)&h1);
        }
    }
    // W^T tile: coalesced read of W[f][c], transposed 2B store
#pragma unroll 4
    for (int i = t; i < 128 * 128; i += 256) {
        int f = i >> 7, c = i & 127;
        Wt[c * APAD + f] = __float2half_rn(weight[i]);
    }
    __syncthreads();

    float c[16][4];
#pragma unroll
    for (int j = 0; j < 16; j++)
#pragma unroll
        for (int i = 0; i < 4; i++) c[j][i] = 0.0f;

    int m0 = wid * 16;
    const __half* ar0 = As + (m0 + gid) * APAD + 2 * tig;
    const __half* ar1 = ar0 + 8 * APAD;

#pragma unroll
    for (int ks = 0; ks < 8; ks++) {
        int k0 = ks * 16;
        uint32_t a0 = *(const uint32_t*)(ar0 + k0);
        uint32_t a1 = *(const uint32_t*)(ar1 + k0);
        uint32_t a2 = *(const uint32_t*)(ar0 + k0 + 8);
        uint32_t a3 = *(const uint32_t*)(ar1 + k0 + 8);
        const __half* bp = Wt + gid * APAD + k0 + 2 * tig;
#pragma unroll
        for (int j = 0; j < 16; j++) {
            uint32_t b0 = *(const uint32_t*)(bp);
            uint32_t b1 = *(const uint32_t*)(bp + 8);
            bp += 8 * APAD;
            asm volatile(
                "mma.sync.aligned.m16n8k16.row.col.f32.f16.f16.f32 "
                "{%0,%1,%2,%3}, {%4,%5,%6,%7}, {%8,%9}, {%0,%1,%2,%3};"
                : "+f"(c[j][0]), "+f"(c[j][1]), "+f"(c[j][2]), "+f"(c[j][3])
                : "r"(a0), "r"(a1), "r"(a2), "r"(a3), "r"(b0), "r"(b1));
        }
    }

    // Epilogue: frags -> padded staging (reuses A region) -> coalesced uint4 STG
    __syncthreads();
    uint32_t* stg = (uint32_t*)As;     // 128 x SPAD u32 = 34816 B (= A region)
#pragma unroll
    for (int j = 0; j < 16; j++) {
        __half2 h0 = __floats2half2_rn(c[j][0], c[j][1]);
        __half2 h1 = __floats2half2_rn(c[j][2], c[j][3]);
        stg[(m0 + gid)     * SPAD + 4 * j + tig] = *(uint32_t*)&h0;
        stg[(m0 + gid + 8) * SPAD + 4 * j + tig] = *(uint32_t*)&h1;
    }
    __syncthreads();
    uint4* outp = (uint4*)(g_x16 + r0 * (N_FEAT / 2));
#pragma unroll
    for (int i = 0; i < 8; i++) {
        int idx = t + i * 256;         // 2048 uint4 = 128 rows x 16
        int rr = idx >> 4, j4 = idx & 15;
        const uint32_t* p = stg + rr * SPAD + j4 * 4;
        outp[idx] = make_uint4(p[0], p[1], p[2], p[3]);
    }
}

// ---------------------------------------------------------------------------
// CSR fill: bucket src ids by dst. Small 4B atomics only; zero smem.
// ---------------------------------------------------------------------------
__global__ void fill_kernel(const void* __restrict__ src, const void* __restrict__ dst) {
    int is64 = g_is64;
    int w = blockIdx.y;
    long long base = (long long)w * N_EDGES;
    for (int e = blockIdx.x * blockDim.x + threadIdx.x; e < N_EDGES;
         e += gridDim.x * blockDim.x) {
        int s = load_idx(src, base + e, is64);
        int d = load_idx(dst, base + e, is64);
        unsigned pos = g_off[w * N_NODES + d] + atomicAdd(&g_cur[w * N_NODES + d], 1u);
        g_csr[base + pos] = s;
    }
}

// ---------------------------------------------------------------------------
// Gather: out[r] = indeg(r)^-1/2 * sum_{s in CSR[r]} X16[s] + bias.
// Warp per row, zero smem -> full occupancy; pure L2-BW bound.
// ---------------------------------------------------------------------------
__global__ void __launch_bounds__(256)
gather_kernel(const float* __restrict__ bias, float* __restrict__ out) {
    int lane = threadIdx.x & 31;
    long long r = (long long)((blockIdx.x * blockDim.x + threadIdx.x) >> 5);
    if (r >= N_ROWS) return;
    int w = (int)(r / N_NODES);

    unsigned st  = g_off[r];
    unsigned deg = g_deg[N_ROWS + r];
    const int* ep = g_csr + (long long)w * N_EDGES + st;
    const __half2* xw = g_x16 + (long long)w * N_NODES * (N_FEAT / 2);

    float4 acc = make_float4(0.f, 0.f, 0.f, 0.f);
#pragma unroll 4
    for (unsigned j = 0; j < deg; j++) {
        int s = ep[j];                                  // broadcast 4B
        uint2 u = *(const uint2*)(xw + (long long)s * (N_FEAT / 2) + lane * 2);
        float2 f01 = __half22float2(*(const __half2*)&u.x);
        float2 f23 = __half22float2(*(const __half2*)&u.y);
        acc.x += f01.x; acc.y += f01.y;
        acc.z += f23.x; acc.w += f23.y;
    }
    float si = g_dinv[N_ROWS + r];
    float4 bv = *((const float4*)bias + lane);
    float4 o;
    o.x = acc.x * si + bv.x;
    o.y = acc.y * si + bv.y;
    o.z = acc.z * si + bv.z;
    o.w = acc.w * si + bv.w;
    *((float4*)(out + r * N_FEAT) + lane) = o;
}

// ---------------------------------------------------------------------------
extern "C" void kernel_launch(void* const* d_in, const int* in_sizes, int n_in,
                              void* d_out, int out_size) {
    const float* feats  = (const float*)d_in[0];
    const float* weight = (const float*)d_in[1];
    const float* bias   = (const float*)d_in[2];
    const void*  src    = d_in[3];
    const void*  dst    = d_in[4];
    float* out = (float*)d_out;

    void* p = nullptr;
    cudaGetSymbolAddress(&p, g_deg);
    cudaMemsetAsync(p, 0, sizeof(unsigned) * 2 * N_ROWS);
    cudaGetSymbolAddress(&p, g_cur);
    cudaMemsetAsync(p, 0, sizeof(unsigned) * N_ROWS);

    detect_idx_kernel<<<1, 256>>>((const unsigned int*)src);

    dim3 dgrid(2048, N_WORKERS);
    degree_kernel<<<dgrid, 256>>>(src, dst);

    dim3 sgrid1(N_SBLK, N_WORKERS);
    scan1_kernel<<<sgrid1, SCAN_B>>>();
    scan2_kernel<<<1, 128>>>();
    dim3 sgrid3((N_NODES + 255) / 256, N_WORKERS);
    scan3_kernel<<<sgrid3, 256>>>();   // also produces dinv (out+in)

    cudaFuncSetAttribute(gemm_mma_kernel, cudaFuncAttributeMaxDynamicSharedMemorySize,
                         SMEM_TOT);
    gemm_mma_kernel<<<N_ROWS / 128, 256, SMEM_TOT>>>(feats, weight);

    fill_kernel<<<dgrid, 256>>>(src, dst);

    gather_kernel<<<(N_ROWS * 32 + 255) / 256, 256>>>(bias, out);
}